// round 4
// baseline (speedup 1.0000x reference)
#include <cuda_runtime.h>
#include <math.h>

#define Nb 2
#define T  2048
#define H  256
#define NH 8
#define D  32
#define SCALE 17.677669529663689f   /* (1/sqrt(32)) / 0.01 */
#define NEGBIG (-1e30f)

typedef unsigned long long u64;

/* ---- packed f32x2 helpers (ptxas never emits FFMA2 from C++) ---- */
__device__ __forceinline__ void fma2(u64& d, u64 a, u64 b) {
    asm("fma.rn.f32x2 %0, %1, %2, %0;" : "+l"(d) : "l"(a), "l"(b));
}
__device__ __forceinline__ u64 pack2(float x, float y) {
    u64 r; asm("mov.b64 %0, {%1, %2};" : "=l"(r) : "f"(x), "f"(y)); return r;
}
__device__ __forceinline__ float2 unpack2(u64 v) {
    float2 f; asm("mov.b64 {%0, %1}, %2;" : "=f"(f.x), "=f"(f.y) : "l"(v)); return f;
}
__device__ __forceinline__ u64 mul2(u64 a, u64 b) {
    u64 r; asm("mul.rn.f32x2 %0, %1, %2;" : "=l"(r) : "l"(a), "l"(b)); return r;
}

/* Scratch: __device__ globals (no allocations allowed). */
__device__ __align__(16) float g_Qh[Nb*NH*T*D];   /* [n][h][t][d] */
__device__ __align__(16) float g_Kh[Nb*NH*T*D];
__device__ __align__(16) float g_Vh[Nb*NH*T*D];
__device__ __align__(16) float g_ctx[Nb*T*H];     /* [n][t][h*D+d] */
__device__ float g_kmask[Nb*T];
__device__ float g_qmask[Nb*T];

/* ------------------------------------------------------------------ */
__global__ void mask_kernel(const float* __restrict__ Q,
                            const float* __restrict__ K) {
    int row = blockIdx.x;
    const float* src = blockIdx.y ? K : Q;
    float* dst       = blockIdx.y ? g_kmask : g_qmask;
    int t = threadIdx.x;                     /* 128 threads */
    float s = fabsf(src[row*H + t]) + fabsf(src[row*H + t + 128]);
    __shared__ float red[4];
    #pragma unroll
    for (int o = 16; o; o >>= 1) s += __shfl_xor_sync(0xffffffffu, s, o);
    if ((t & 31) == 0) red[t >> 5] = s;
    __syncthreads();
    if (t == 0) {
        float tot = red[0] + red[1] + red[2] + red[3];
        dst[row] = (tot != 0.0f) ? 1.0f : 0.0f;
    }
}

/* ------------------------------------------------------------------ */
/* Fused projection: dst[n][h][t][d] = relu(X @ W + b), head-major.   */
__global__ void __launch_bounds__(256) proj_kernel(
        const float* __restrict__ Q, const float* __restrict__ K,
        const float* __restrict__ V,
        const float* __restrict__ Wq, const float* __restrict__ Wk,
        const float* __restrict__ Wv,
        const float* __restrict__ bq, const float* __restrict__ bk,
        const float* __restrict__ bv) {
    int sel = blockIdx.z;
    const float* X = (sel == 0) ? Q  : (sel == 1) ? K  : V;
    const float* W = (sel == 0) ? Wq : (sel == 1) ? Wk : Wv;
    const float* b = (sel == 0) ? bq : (sel == 1) ? bk : bv;
    float* dst     = (sel == 0) ? g_Qh : (sel == 1) ? g_Kh : g_Vh;

    int m0 = blockIdx.y * 64;
    int n0 = blockIdx.x * 64;

    __shared__ __align__(16) float Xst[32][68];  /* [k][m] transposed */
    __shared__ __align__(16) float Wsh[32][68];  /* [k][n]            */

    int tid = threadIdx.x;
    int ty = tid >> 4, tx = tid & 15;
    u64 acc2[4][2] = {};

    for (int k0 = 0; k0 < H; k0 += 32) {
        __syncthreads();
        #pragma unroll
        for (int it = 0; it < 8; ++it) {
            int e = tid + it * 256;
            int r = e >> 5, c = e & 31;
            Xst[c][r] = X[(m0 + r) * H + k0 + c];
            int r2 = e >> 6, c2 = e & 63;
            Wsh[r2][c2] = W[(k0 + r2) * H + n0 + c2];
        }
        __syncthreads();
        #pragma unroll
        for (int kk = 0; kk < 32; ++kk) {
            float4 a = *(const float4*)&Xst[kk][4 * ty];
            ulonglong2 bb = *(const ulonglong2*)&Wsh[kk][4 * tx];
            u64 a0 = pack2(a.x, a.x), a1 = pack2(a.y, a.y);
            u64 a2 = pack2(a.z, a.z), a3 = pack2(a.w, a.w);
            fma2(acc2[0][0], a0, bb.x); fma2(acc2[0][1], a0, bb.y);
            fma2(acc2[1][0], a1, bb.x); fma2(acc2[1][1], a1, bb.y);
            fma2(acc2[2][0], a2, bb.x); fma2(acc2[2][1], a2, bb.y);
            fma2(acc2[3][0], a3, bb.x); fma2(acc2[3][1], a3, bb.y);
        }
    }

    int c0 = n0 + 4 * tx;
    int hh = c0 >> 5, d0 = c0 & 31;
    float b0 = b[c0+0], b1 = b[c0+1], b2 = b[c0+2], b3 = b[c0+3];
    #pragma unroll
    for (int i = 0; i < 4; ++i) {
        int m  = m0 + 4 * ty + i;
        int nn = m >> 11, tt = m & 2047;
        float2 lo = unpack2(acc2[i][0]), hi = unpack2(acc2[i][1]);
        float4 o;
        o.x = fmaxf(lo.x + b0, 0.0f);
        o.y = fmaxf(lo.y + b1, 0.0f);
        o.z = fmaxf(hi.x + b2, 0.0f);
        o.w = fmaxf(hi.y + b3, 0.0f);
        *(float4*)&dst[(((nn * NH) + hh) * T + tt) * D + d0] = o;
    }
}

/* ------------------------------------------------------------------ */
/* Flash attention. Grid (T/64, NH, Nb), 256 threads, 4 blocks/SM.    */
/* Smem 53.5KB: Qtd(dup pairs) + Kt[d][k] + Vs[k][d] + Ps[q][k].      */
__global__ void __launch_bounds__(256, 4) attn_kernel() {
    int q0 = blockIdx.x * 64;
    int hh = blockIdx.y, nn = blockIdx.z;
    const float* Qh = g_Qh + (size_t)(nn * NH + hh) * T * D;
    const float* Kh = g_Kh + (size_t)(nn * NH + hh) * T * D;
    const float* Vh = g_Vh + (size_t)(nn * NH + hh) * T * D;

    __shared__ __align__(16) float Qtd[32][136];  /* [d][2q] duplicated pairs */
    __shared__ __align__(16) float Kt[32][68];    /* [d][k] */
    __shared__ __align__(16) float Vs[64][36];    /* [k][d] natural */
    __shared__ __align__(16) float Ps[64][68];    /* [q][k] */
    __shared__ float m_s[64], l_s[64], fs_s[64];

    int tid = threadIdx.x;
    int qg = tid >> 4, kg = tid & 15;     /* phase 1: 4q x 4k */
    int qp = tid >> 3, dp = tid & 7;      /* phase 2: 2q x 4d */

    /* Q fill: duplicated (q,q) pairs so phase-1 FFMA2 needs no packs */
    #pragma unroll
    for (int it = 0; it < 8; ++it) {
        int e = tid + it * 256;
        int r = e >> 5, c = e & 31;
        float v = Qh[(q0 + r) * D + c];
        *(float2*)&Qtd[c][2 * r] = make_float2(v, v);
    }
    if (tid < 64) { m_s[tid] = -1e30f; l_s[tid] = 0.0f; fs_s[tid] = 0.0f; }
    u64 O2[2][2] = {};                    /* [q-row][d-pair] */

    for (int kt = 0; kt < T / 64; ++kt) {
        int k0 = kt * 64;
        __syncthreads();
        #pragma unroll
        for (int it = 0; it < 8; ++it) {
            int e = tid + it * 256;
            int r = e >> 5, c = e & 31;
            Kt[c][r] = Kh[(k0 + r) * D + c];   /* transposed */
            Vs[r][c] = Vh[(k0 + r) * D + c];   /* natural    */
        }
        __syncthreads();

        /* ---- Phase 1: S = Q K^T via packed FFMA2 ---- */
        u64 acc2[4][2] = {};
        #pragma unroll
        for (int dd = 0; dd < 32; ++dd) {
            ulonglong2 qa = *(const ulonglong2*)&Qtd[dd][8 * qg];
            ulonglong2 qb = *(const ulonglong2*)&Qtd[dd][8 * qg + 4];
            ulonglong2 kk = *(const ulonglong2*)&Kt[dd][4 * kg];
            fma2(acc2[0][0], qa.x, kk.x); fma2(acc2[0][1], qa.x, kk.y);
            fma2(acc2[1][0], qa.y, kk.x); fma2(acc2[1][1], qa.y, kk.y);
            fma2(acc2[2][0], qb.x, kk.x); fma2(acc2[2][1], qb.x, kk.y);
            fma2(acc2[3][0], qb.y, kk.x); fma2(acc2[3][1], qb.y, kk.y);
        }
        float msk[4];
        #pragma unroll
        for (int j = 0; j < 4; ++j)
            msk[j] = g_kmask[nn * T + k0 + 4 * kg + j];

        #pragma unroll
        for (int i = 0; i < 4; ++i) {
            int q = 4 * qg + i;
            float2 lo = unpack2(acc2[i][0]), hi = unpack2(acc2[i][1]);
            float s0 = (msk[0] != 0.0f) ? lo.x * SCALE : NEGBIG;
            float s1 = (msk[1] != 0.0f) ? lo.y * SCALE : NEGBIG;
            float s2 = (msk[2] != 0.0f) ? hi.x * SCALE : NEGBIG;
            float s3 = (msk[3] != 0.0f) ? hi.y * SCALE : NEGBIG;
            float mx = fmaxf(fmaxf(s0, s1), fmaxf(s2, s3));
            #pragma unroll
            for (int o = 8; o; o >>= 1)
                mx = fmaxf(mx, __shfl_xor_sync(0xffffffffu, mx, o));
            float mo = m_s[q];
            float nm = fmaxf(mo, mx);
            float p0 = __expf(s0 - nm), p1 = __expf(s1 - nm);
            float p2 = __expf(s2 - nm), p3 = __expf(s3 - nm);
            float sum = (p0 + p1) + (p2 + p3);
            #pragma unroll
            for (int o = 8; o; o >>= 1)
                sum += __shfl_xor_sync(0xffffffffu, sum, o);
            /* key Tk-1 participates in softmax denom but not in ctx */
            float4 pw;
            pw.x = (k0 + 4*kg + 0 == T - 1) ? 0.0f : p0;
            pw.y = (k0 + 4*kg + 1 == T - 1) ? 0.0f : p1;
            pw.z = (k0 + 4*kg + 2 == T - 1) ? 0.0f : p2;
            pw.w = (k0 + 4*kg + 3 == T - 1) ? 0.0f : p3;
            *(float4*)&Ps[q][4 * kg] = pw;
            if (kg == 0) {
                float f = __expf(mo - nm);
                l_s[q]  = l_s[q] * f + sum;
                m_s[q]  = nm;
                fs_s[q] = f;
            }
        }
        __syncthreads();

        /* ---- Phase 2: O += P V, packed over d ---- */
        {
            float fA = fs_s[2 * qp],  fB = fs_s[2 * qp + 1];
            u64 fA2 = pack2(fA, fA),  fB2 = pack2(fB, fB);
            O2[0][0] = mul2(O2[0][0], fA2); O2[0][1] = mul2(O2[0][1], fA2);
            O2[1][0] = mul2(O2[1][0], fB2); O2[1][1] = mul2(O2[1][1], fB2);
        }
        #pragma unroll
        for (int kc = 0; kc < 64; kc += 4) {
            ulonglong2 v0 = *(const ulonglong2*)&Vs[kc + 0][4 * dp];
            ulonglong2 v1 = *(const ulonglong2*)&Vs[kc + 1][4 * dp];
            ulonglong2 v2 = *(const ulonglong2*)&Vs[kc + 2][4 * dp];
            ulonglong2 v3 = *(const ulonglong2*)&Vs[kc + 3][4 * dp];
            float4 pa = *(const float4*)&Ps[2 * qp][kc];
            float4 pb = *(const float4*)&Ps[2 * qp + 1][kc];
            u64 t;
            t = pack2(pa.x, pa.x); fma2(O2[0][0], t, v0.x); fma2(O2[0][1], t, v0.y);
            t = pack2(pa.y, pa.y); fma2(O2[0][0], t, v1.x); fma2(O2[0][1], t, v1.y);
            t = pack2(pa.z, pa.z); fma2(O2[0][0], t, v2.x); fma2(O2[0][1], t, v2.y);
            t = pack2(pa.w, pa.w); fma2(O2[0][0], t, v3.x); fma2(O2[0][1], t, v3.y);
            t = pack2(pb.x, pb.x); fma2(O2[1][0], t, v0.x); fma2(O2[1][1], t, v0.y);
            t = pack2(pb.y, pb.y); fma2(O2[1][0], t, v1.x); fma2(O2[1][1], t, v1.y);
            t = pack2(pb.z, pb.z); fma2(O2[1][0], t, v2.x); fma2(O2[1][1], t, v2.y);
            t = pack2(pb.w, pb.w); fma2(O2[1][0], t, v3.x); fma2(O2[1][1], t, v3.y);
        }
    }

    #pragma unroll
    for (int r = 0; r < 2; ++r) {
        int q = 2 * qp + r;
        float inv = g_qmask[nn * T + q0 + q] / l_s[q];
        float2 a = unpack2(O2[r][0]), b = unpack2(O2[r][1]);
        float4 o = make_float4(a.x * inv, a.y * inv, b.x * inv, b.y * inv);
        *(float4*)&g_ctx[(size_t)(nn * T + q0 + q) * H + hh * D + 4 * dp] = o;
    }
}

/* ------------------------------------------------------------------ */
__global__ void __launch_bounds__(256) ln_kernel(
        const float* __restrict__ gamma, const float* __restrict__ beta,
        float* __restrict__ out, float* __restrict__ wout) {
    int row = blockIdx.x;
    int t = threadIdx.x;
    float x = g_ctx[(size_t)row * H + t];
    __shared__ float rs[8], rq[8];
    float s = x, q = x * x;
    #pragma unroll
    for (int o = 16; o; o >>= 1) {
        s += __shfl_xor_sync(0xffffffffu, s, o);
        q += __shfl_xor_sync(0xffffffffu, q, o);
    }
    if ((t & 31) == 0) { rs[t >> 5] = s; rq[t >> 5] = q; }
    __syncthreads();
    float ts = 0.0f, tq = 0.0f;
    #pragma unroll
    for (int i = 0; i < 8; ++i) { ts += rs[i]; tq += rq[i]; }
    float mu  = ts * (1.0f / H);
    float var = tq * (1.0f / H) - mu * mu;
    float inv = rsqrtf(var + 1e-5f);
    out[(size_t)row * H + t] = (x - mu) * inv * gamma[t] + beta[t];
    if (t == 0)
        wout[row] = g_qmask[row] * (1.0f / (float)T);
}

/* ------------------------------------------------------------------ */
extern "C" void kernel_launch(void* const* d_in, const int* in_sizes, int n_in,
                              void* d_out, int out_size) {
    const float* Q  = (const float*)d_in[0];
    const float* K  = (const float*)d_in[1];
    const float* V  = (const float*)d_in[2];
    const float* Wq = (const float*)d_in[3];
    const float* bq = (const float*)d_in[4];
    const float* Wk = (const float*)d_in[5];
    const float* bk = (const float*)d_in[6];
    const float* Wv = (const float*)d_in[7];
    const float* bv = (const float*)d_in[8];
    const float* gamma = (const float*)d_in[9];
    const float* beta  = (const float*)d_in[10];

    float* out  = (float*)d_out;
    float* wout = out + (out_size - Nb * T);

    mask_kernel<<<dim3(Nb * T, 2), 128>>>(Q, K);
    proj_kernel<<<dim3(H / 64, (Nb * T) / 64, 3), 256>>>(Q, K, V,
                                                         Wq, Wk, Wv,
                                                         bq, bk, bv);
    attn_kernel<<<dim3(T / 64, NH, Nb), 256>>>();
    ln_kernel<<<Nb * T, 256>>>(gamma, beta, out, wout);
}

// round 6
// speedup vs baseline: 1.7353x; 1.7353x over previous
#include <cuda_runtime.h>
#include <cstdint>
#include <math.h>

#define Nb 2
#define T  2048
#define H  256
#define NH 8
#define D  32
#define SCALE 17.677669529663689f

typedef unsigned long long u64;
typedef uint32_t u32;

__device__ __forceinline__ void fma2(u64& d, u64 a, u64 b) {
    asm("fma.rn.f32x2 %0, %1, %2, %0;" : "+l"(d) : "l"(a), "l"(b));
}
__device__ __forceinline__ u64 pack2(float x, float y) {
    u64 r; asm("mov.b64 %0, {%1, %2};" : "=l"(r) : "f"(x), "f"(y)); return r;
}
__device__ __forceinline__ float2 unpack2(u64 v) {
    float2 f; asm("mov.b64 {%0, %1}, %2;" : "=f"(f.x), "=f"(f.y) : "l"(v)); return f;
}
__device__ __forceinline__ u32 tf32_hi(float x) {
    u32 h; asm("cvt.rna.tf32.f32 %0, %1;" : "=r"(h) : "f"(x)); return h;
}
/* hi/lo tf32 split: x = hi + lo to ~2^-22 */
__device__ __forceinline__ void tf32_split(float x, u32& hi, u32& lo) {
    hi = tf32_hi(x);
    lo = tf32_hi(x - __uint_as_float(hi));
}
#define MMA(c, a, b0, b1) \
    asm volatile("mma.sync.aligned.m16n8k8.row.col.f32.tf32.tf32.f32 " \
        "{%0,%1,%2,%3}, {%4,%5,%6,%7}, {%8,%9}, {%0,%1,%2,%3};" \
        : "+f"((c)[0]), "+f"((c)[1]), "+f"((c)[2]), "+f"((c)[3]) \
        : "r"((a)[0]), "r"((a)[1]), "r"((a)[2]), "r"((a)[3]), "r"(b0), "r"(b1))

__device__ __align__(16) float g_Qh[Nb*NH*T*D];
__device__ __align__(16) float g_Kh[Nb*NH*T*D];
__device__ __align__(16) float g_Vh[Nb*NH*T*D];
__device__ __align__(16) float g_ctx[Nb*T*H];
__device__ float g_kbias[Nb*T];   /* 0 or -1e35 */
__device__ float g_qmask[Nb*T];

/* ------------------------------------------------------------------ */
__global__ void mask_kernel(const float* __restrict__ Q,
                            const float* __restrict__ K) {
    int row = blockIdx.x;
    const float* src = blockIdx.y ? K : Q;
    int t = threadIdx.x;
    float s = fabsf(src[row*H + t]) + fabsf(src[row*H + t + 128]);
    __shared__ float red[4];
    #pragma unroll
    for (int o = 16; o; o >>= 1) s += __shfl_xor_sync(0xffffffffu, s, o);
    if ((t & 31) == 0) red[t >> 5] = s;
    __syncthreads();
    if (t == 0) {
        float tot = red[0] + red[1] + red[2] + red[3];
        if (blockIdx.y) g_kbias[row] = (tot != 0.0f) ? 0.0f : -1e35f;
        else            g_qmask[row] = (tot != 0.0f) ? 1.0f : 0.0f;
    }
}

/* ------------------------------------------------------------------ */
__global__ void __launch_bounds__(256) proj_kernel(
        const float* __restrict__ Q, const float* __restrict__ K,
        const float* __restrict__ V,
        const float* __restrict__ Wq, const float* __restrict__ Wk,
        const float* __restrict__ Wv,
        const float* __restrict__ bq, const float* __restrict__ bk,
        const float* __restrict__ bv) {
    int sel = blockIdx.z;
    const float* X = (sel == 0) ? Q  : (sel == 1) ? K  : V;
    const float* W = (sel == 0) ? Wq : (sel == 1) ? Wk : Wv;
    const float* b = (sel == 0) ? bq : (sel == 1) ? bk : bv;
    float* dst     = (sel == 0) ? g_Qh : (sel == 1) ? g_Kh : g_Vh;
    int m0 = blockIdx.y * 64, n0 = blockIdx.x * 64;
    __shared__ __align__(16) float Xst[32][68];
    __shared__ __align__(16) float Wsh[32][68];
    int tid = threadIdx.x, ty = tid >> 4, tx = tid & 15;
    u64 acc2[4][2] = {};
    for (int k0 = 0; k0 < H; k0 += 32) {
        __syncthreads();
        #pragma unroll
        for (int it = 0; it < 8; ++it) {
            int e = tid + it * 256;
            int r = e >> 5, c = e & 31;
            Xst[c][r] = X[(m0 + r) * H + k0 + c];
            int r2 = e >> 6, c2 = e & 63;
            Wsh[r2][c2] = W[(k0 + r2) * H + n0 + c2];
        }
        __syncthreads();
        #pragma unroll
        for (int kk = 0; kk < 32; ++kk) {
            float4 a = *(const float4*)&Xst[kk][4 * ty];
            ulonglong2 bb = *(const ulonglong2*)&Wsh[kk][4 * tx];
            u64 a0 = pack2(a.x, a.x), a1 = pack2(a.y, a.y);
            u64 a2 = pack2(a.z, a.z), a3 = pack2(a.w, a.w);
            fma2(acc2[0][0], a0, bb.x); fma2(acc2[0][1], a0, bb.y);
            fma2(acc2[1][0], a1, bb.x); fma2(acc2[1][1], a1, bb.y);
            fma2(acc2[2][0], a2, bb.x); fma2(acc2[2][1], a2, bb.y);
            fma2(acc2[3][0], a3, bb.x); fma2(acc2[3][1], a3, bb.y);
        }
    }
    int c0 = n0 + 4 * tx, hh = c0 >> 5, d0 = c0 & 31;
    float b0 = b[c0+0], b1 = b[c0+1], b2 = b[c0+2], b3 = b[c0+3];
    #pragma unroll
    for (int i = 0; i < 4; ++i) {
        int m = m0 + 4 * ty + i, nn = m >> 11, tt = m & 2047;
        float2 lo = unpack2(acc2[i][0]), hi = unpack2(acc2[i][1]);
        float4 o;
        o.x = fmaxf(lo.x + b0, 0.0f); o.y = fmaxf(lo.y + b1, 0.0f);
        o.z = fmaxf(hi.x + b2, 0.0f); o.w = fmaxf(hi.y + b3, 0.0f);
        *(float4*)&dst[(((nn * NH) + hh) * T + tt) * D + d0] = o;
    }
}

/* ------------------------------------------------------------------ */
/* 3xTF32 mma flash attention. Grid (16, NH, Nb), 128 thr (4 warps).  */
/* Warp owns 32 q-rows (2 m16 frags). K macro-tile 64, halves of 32.  */
#define KPITCH 68
#define VPITCH 36
#define PPITCH 36
#define SM_FLOATS (2*32*KPITCH + 2*64*VPITCH + 4*32*PPITCH + 64)
#define SMEM_BYTES (SM_FLOATS * 4)

__global__ void __launch_bounds__(128, 2) attn_kernel() {
    extern __shared__ __align__(16) float dsm[];
    float* Khi = dsm;                       /* [32][KPITCH] d-major   */
    float* Klo = Khi + 32 * KPITCH;
    float* Vhi = Klo + 32 * KPITCH;         /* [64][VPITCH] key-major */
    float* Vlo = Vhi + 64 * VPITCH;
    float* Ps  = Vlo + 64 * VPITCH;         /* [4][32][PPITCH]        */
    float* bias_s = Ps + 4 * 32 * PPITCH;

    int tid = threadIdx.x, w = tid >> 5, lane = tid & 31;
    int g = lane >> 2, tq = lane & 3;
    int q0 = blockIdx.x * 128, hh = blockIdx.y, nn = blockIdx.z;
    const float* Qg = g_Qh + (size_t)(nn * NH + hh) * T * D;
    const float* Kg = g_Kh + (size_t)(nn * NH + hh) * T * D;
    const float* Vg = g_Vh + (size_t)(nn * NH + hh) * T * D;
    float* Pw = Ps + w * 32 * PPITCH;

    /* Q fragments (loop-invariant): rows q0+32w+16m+g(+8), cols 8ks+tq(+4) */
    u32 qh[2][4][4], ql[2][4][4];
    #pragma unroll
    for (int m = 0; m < 2; ++m) {
        int r0 = (q0 + 32 * w + 16 * m + g) * D;
        int r1 = r0 + 8 * D;
        #pragma unroll
        for (int ks = 0; ks < 4; ++ks) {
            tf32_split(Qg[r0 + 8*ks + tq],     qh[m][ks][0], ql[m][ks][0]);
            tf32_split(Qg[r1 + 8*ks + tq],     qh[m][ks][1], ql[m][ks][1]);
            tf32_split(Qg[r0 + 8*ks + tq + 4], qh[m][ks][2], ql[m][ks][2]);
            tf32_split(Qg[r1 + 8*ks + tq + 4], qh[m][ks][3], ql[m][ks][3]);
        }
    }
    float O[2][4][4];
    #pragma unroll
    for (int m = 0; m < 2; ++m)
        #pragma unroll
        for (int nf = 0; nf < 4; ++nf)
            #pragma unroll
            for (int c = 0; c < 4; ++c) O[m][nf][c] = 0.0f;
    float mrun[2][2] = {{-1e30f,-1e30f},{-1e30f,-1e30f}};
    float lrun[2][2] = {{0.f,0.f},{0.f,0.f}};

    for (int kt = 0; kt < T / 64; ++kt) {
        int k0 = kt * 64;
        __syncthreads();
        #pragma unroll
        for (int i = 0; i < 16; ++i) {     /* K,V tiles -> hi/lo smem */
            int idx = tid + 128 * i;
            int row = idx >> 5, c = idx & 31;
            u32 hb, lb;
            tf32_split(Kg[(k0 + row) * D + c], hb, lb);
            Khi[c * KPITCH + row] = __uint_as_float(hb);
            Klo[c * KPITCH + row] = __uint_as_float(lb);
            tf32_split(Vg[(k0 + row) * D + c], hb, lb);
            Vhi[row * VPITCH + c] = __uint_as_float(hb);
            Vlo[row * VPITCH + c] = __uint_as_float(lb);
        }
        if (tid < 64) bias_s[tid] = g_kbias[nn * T + k0 + tid];
        __syncthreads();

        #pragma unroll
        for (int h = 0; h < 2; ++h) {
            /* ---- S = Q K^T (3xTF32) ---- */
            float s[2][4][4];
            #pragma unroll
            for (int m = 0; m < 2; ++m)
                #pragma unroll
                for (int j = 0; j < 4; ++j)
                    #pragma unroll
                    for (int c = 0; c < 4; ++c) s[m][j][c] = 0.0f;
            #pragma unroll
            for (int ks = 0; ks < 4; ++ks) {
                u32 bh[4][2], bl[4][2];
                #pragma unroll
                for (int j = 0; j < 4; ++j) {
                    int col = 32 * h + 8 * j + g;
                    bh[j][0] = __float_as_uint(Khi[(8*ks + tq)     * KPITCH + col]);
                    bh[j][1] = __float_as_uint(Khi[(8*ks + tq + 4) * KPITCH + col]);
                    bl[j][0] = __float_as_uint(Klo[(8*ks + tq)     * KPITCH + col]);
                    bl[j][1] = __float_as_uint(Klo[(8*ks + tq + 4) * KPITCH + col]);
                }
                #pragma unroll
                for (int m = 0; m < 2; ++m)
                    #pragma unroll
                    for (int j = 0; j < 4; ++j) {
                        MMA(s[m][j], qh[m][ks], bh[j][0], bh[j][1]);
                        MMA(s[m][j], ql[m][ks], bh[j][0], bh[j][1]);
                        MMA(s[m][j], qh[m][ks], bl[j][0], bl[j][1]);
                    }
            }

            /* ---- softmax (fragment-resident) ---- */
            float2 bb[4];
            #pragma unroll
            for (int j = 0; j < 4; ++j)
                bb[j] = *(float2*)&bias_s[32 * h + 8 * j + 2 * tq];
            #pragma unroll
            for (int m = 0; m < 2; ++m)
                #pragma unroll
                for (int rg = 0; rg < 2; ++rg) {
                    float zv[8];
                    #pragma unroll
                    for (int j = 0; j < 4; ++j) {
                        zv[2*j]   = fmaf(s[m][j][2*rg],   SCALE, bb[j].x);
                        zv[2*j+1] = fmaf(s[m][j][2*rg+1], SCALE, bb[j].y);
                    }
                    float mx = zv[0];
                    #pragma unroll
                    for (int e = 1; e < 8; ++e) mx = fmaxf(mx, zv[e]);
                    mx = fmaxf(mx, __shfl_xor_sync(0xffffffffu, mx, 1));
                    mx = fmaxf(mx, __shfl_xor_sync(0xffffffffu, mx, 2));
                    float mn = fmaxf(mrun[m][rg], mx);
                    float fr = __expf(mrun[m][rg] - mn);
                    mrun[m][rg] = mn;
                    float sum = 0.0f;
                    #pragma unroll
                    for (int j = 0; j < 4; ++j) {
                        float p0 = __expf(zv[2*j]   - mn);
                        float p1 = __expf(zv[2*j+1] - mn);
                        sum += p0 + p1;
                        s[m][j][2*rg] = p0; s[m][j][2*rg+1] = p1;
                    }
                    sum += __shfl_xor_sync(0xffffffffu, sum, 1);
                    sum += __shfl_xor_sync(0xffffffffu, sum, 2);
                    lrun[m][rg] = lrun[m][rg] * fr + sum;
                    #pragma unroll
                    for (int nf = 0; nf < 4; ++nf) {
                        O[m][nf][2*rg]   *= fr;
                        O[m][nf][2*rg+1] *= fr;
                    }
                }

            /* ---- P -> per-warp smem (zero last key in ctx) ---- */
            __syncwarp();
            int kb = k0 + 32 * h + 2 * tq;
            #pragma unroll
            for (int m = 0; m < 2; ++m)
                #pragma unroll
                for (int j = 0; j < 4; ++j) {
                    float p1 = s[m][j][1], p3 = s[m][j][3];
                    if (kb + 8*j + 1 == T - 1) { p1 = 0.0f; p3 = 0.0f; }
                    *(float2*)&Pw[(16*m + g)     * PPITCH + 8*j + 2*tq] =
                        make_float2(s[m][j][0], p1);
                    *(float2*)&Pw[(16*m + 8 + g) * PPITCH + 8*j + 2*tq] =
                        make_float2(s[m][j][2], p3);
                }
            __syncwarp();

            /* ---- O += P V (3xTF32) ---- */
            #pragma unroll
            for (int ks = 0; ks < 4; ++ks) {
                u32 ph[2][4], pl[2][4];
                #pragma unroll
                for (int m = 0; m < 2; ++m) {
                    tf32_split(Pw[(16*m + g)   * PPITCH + 8*ks + tq],     ph[m][0], pl[m][0]);
                    tf32_split(Pw[(16*m + 8+g) * PPITCH + 8*ks + tq],     ph[m][1], pl[m][1]);
                    tf32_split(Pw[(16*m + g)   * PPITCH + 8*ks + tq + 4], ph[m][2], pl[m][2]);
                    tf32_split(Pw[(16*m + 8+g) * PPITCH + 8*ks + tq + 4], ph[m][3], pl[m][3]);
                }
                int krow0 = (32*h + 8*ks + tq) * VPITCH;
                int krow1 = (32*h + 8*ks + tq + 4) * VPITCH;
                #pragma unroll
                for (int nf = 0; nf < 4; ++nf) {
                    u32 vh0 = __float_as_uint(Vhi[krow0 + 8*nf + g]);
                    u32 vh1 = __float_as_uint(Vhi[krow1 + 8*nf + g]);
                    u32 vl0 = __float_as_uint(Vlo[krow0 + 8*nf + g]);
                    u32 vl1 = __float_as_uint(Vlo[krow1 + 8*nf + g]);
                    #pragma unroll
                    for (int m = 0; m < 2; ++m) {
                        MMA(O[m][nf], ph[m], vh0, vh1);
                        MMA(O[m][nf], pl[m], vh0, vh1);
                        MMA(O[m][nf], ph[m], vl0, vl1);
                    }
                }
            }
        }
    }

    /* ---- epilogue ---- */
    #pragma unroll
    for (int m = 0; m < 2; ++m)
        #pragma unroll
        for (int rg = 0; rg < 2; ++rg) {
            int row = q0 + 32 * w + 16 * m + 8 * rg + g;
            float inv = g_qmask[nn * T + row] / lrun[m][rg];
            float* dst = &g_ctx[(size_t)(nn * T + row) * H + hh * D];
            #pragma unroll
            for (int nf = 0; nf < 4; ++nf)
                *(float2*)&dst[8*nf + 2*tq] =
                    make_float2(O[m][nf][2*rg] * inv, O[m][nf][2*rg+1] * inv);
        }
}

/* ------------------------------------------------------------------ */
__global__ void __launch_bounds__(256) ln_kernel(
        const float* __restrict__ gamma, const float* __restrict__ beta,
        float* __restrict__ out, float* __restrict__ wout) {
    int row = blockIdx.x, t = threadIdx.x;
    float x = g_ctx[(size_t)row * H + t];
    __shared__ float rs[8], rq[8];
    float s = x, q = x * x;
    #pragma unroll
    for (int o = 16; o; o >>= 1) {
        s += __shfl_xor_sync(0xffffffffu, s, o);
        q += __shfl_xor_sync(0xffffffffu, q, o);
    }
    if ((t & 31) == 0) { rs[t >> 5] = s; rq[t >> 5] = q; }
    __syncthreads();
    float ts = 0.0f, tq = 0.0f;
    #pragma unroll
    for (int i = 0; i < 8; ++i) { ts += rs[i]; tq += rq[i]; }
    float mu = ts * (1.0f / H);
    float var = tq * (1.0f / H) - mu * mu;
    float inv = rsqrtf(var + 1e-5f);
    out[(size_t)row * H + t] = (x - mu) * inv * gamma[t] + beta[t];
    if (t == 0) wout[row] = g_qmask[row] * (1.0f / (float)T);
}

/* ------------------------------------------------------------------ */
extern "C" void kernel_launch(void* const* d_in, const int* in_sizes, int n_in,
                              void* d_out, int out_size) {
    const float* Q  = (const float*)d_in[0];
    const float* K  = (const float*)d_in[1];
    const float* V  = (const float*)d_in[2];
    const float* Wq = (const float*)d_in[3];
    const float* bq = (const float*)d_in[4];
    const float* Wk = (const float*)d_in[5];
    const float* bk = (const float*)d_in[6];
    const float* Wv = (const float*)d_in[7];
    const float* bv = (const float*)d_in[8];
    const float* gamma = (const float*)d_in[9];
    const float* beta  = (const float*)d_in[10];

    float* out  = (float*)d_out;
    float* wout = out + (out_size - Nb * T);

    cudaFuncSetAttribute(attn_kernel,
                         cudaFuncAttributeMaxDynamicSharedMemorySize, SMEM_BYTES);

    mask_kernel<<<dim3(Nb * T, 2), 128>>>(Q, K);
    proj_kernel<<<dim3(H / 64, (Nb * T) / 64, 3), 256>>>(Q, K, V,
                                                         Wq, Wk, Wv,
                                                         bq, bk, bv);
    attn_kernel<<<dim3(T / 128, NH, Nb), 128, SMEM_BYTES>>>();
    ln_kernel<<<Nb * T, 256>>>(gamma, beta, out, wout);
}